// round 2
// baseline (speedup 1.0000x reference)
#include <cuda_runtime.h>
#include <cuda_bf16.h>
#include <cstdint>

#define KTAGS 11
#define NST   9
#define TT    2048
#define BB    4096
#define CH    8            // steps per chunk
#define NCHK  (TT / CH)    // 256
#define DEPTH 4
#define WARPS_PB 10
#define SEQ_PW   3
#define SEQ_PB   (WARPS_PB * SEQ_PW)   // 30
#define THREADS  (WARPS_PB * 32)       // 320
#define START_TAG 10
#define STOP_TAG  9

// One forward step in the scaled linear domain.
// a'_j = exp(f_j) * sum_p E[j,p] * a_p   (optionally renormalized by group max)
template<bool DONORM>
__device__ __forceinline__ void crf_step(float f, int tg,
                                         const float* __restrict__ s_trans,
                                         const float* __restrict__ E,
                                         int base, int j,
                                         float& a, float& gold, int& tagprev, float& L)
{
    float ef = __expf(f);
    float av[NST];
#pragma unroll
    for (int p = 0; p < NST; p++)
        av[p] = __shfl_sync(0xffffffffu, a, base + p);

    float s1 = E[0] * av[0];
    s1 = fmaf(E[1], av[1], s1);
    s1 = fmaf(E[2], av[2], s1);
    s1 = fmaf(E[3], av[3], s1);
    s1 = fmaf(E[4], av[4], s1);
    float s2 = E[5] * av[5];
    s2 = fmaf(E[6], av[6], s2);
    s2 = fmaf(E[7], av[7], s2);
    s2 = fmaf(E[8], av[8], s2);
    float s = s1 + s2;

    if (DONORM) {
        float m = fmaxf(av[0], av[1]);
        m = fmaxf(m, av[2]); m = fmaxf(m, av[3]);
        m = fmaxf(m, av[4]); m = fmaxf(m, av[5]);
        m = fmaxf(m, av[6]); m = fmaxf(m, av[7]);
        m = fmaxf(m, av[8]);
        L += __logf(m);
        s *= (1.0f / m);
    }
    a = ef * s;

    // gold score: feat emission + transition (tag_t, tag_{t-1})
    if (j == tg) gold += f + s_trans[tg * KTAGS + tagprev];
    tagprev = tg;
}

__global__ void __launch_bounds__(THREADS, 1)
crf_nll_kernel(const float* __restrict__ feats,
               const int*   __restrict__ tags,
               const float* __restrict__ trans,
               float* __restrict__ out)
{
    __shared__ __align__(16) float s_feats[DEPTH][WARPS_PB][SEQ_PW][CH * KTAGS]; // 88 floats/seq/chunk
    __shared__ __align__(16) int   s_tags [DEPTH][WARPS_PB][SEQ_PW][CH];
    __shared__ float s_trans[KTAGS * KTAGS];

    const int tid = threadIdx.x;
    if (tid < KTAGS * KTAGS) s_trans[tid] = trans[tid];
    __syncthreads();

    const int w    = tid >> 5;
    const int lane = tid & 31;
    const int g    = (lane / NST < 2) ? (lane / NST) : 2;  // lanes 27..31 shadow group 2
    const int j    = lane % NST;
    const int base = g * NST;
    const int b    = blockIdx.x * SEQ_PB + w * SEQ_PW + g;
    const int bc   = (b < BB) ? b : (BB - 1);

    // exp of this lane's transition row (next = j, prev = p)
    float E[NST];
#pragma unroll
    for (int p = 0; p < NST; p++) E[p] = __expf(s_trans[j * KTAGS + p]);

    // --- cp.async copy plan: 72 16B units per warp-chunk (3 seqs x (22 feat + 2 tag)) ---
    const char* src[3];
    uint32_t    dst0[3];
    int         sstep[3];
    int         dstride[3];
    bool        act[3];
#pragma unroll
    for (int r = 0; r < 3; r++) {
        int u = lane + 32 * r;
        act[r] = (u < 72);
        int uu = act[r] ? u : 0;
        int s  = uu / 24;
        int k  = uu % 24;
        int bs = blockIdx.x * SEQ_PB + w * SEQ_PW + s;
        if (bs >= BB) bs = BB - 1;
        if (k < 22) {
            src[r]     = (const char*)(feats + (size_t)bs * TT * KTAGS) + k * 16;
            sstep[r]   = CH * KTAGS * 4;                    // 352 B per chunk
            dst0[r]    = (uint32_t)__cvta_generic_to_shared(&s_feats[0][w][s][k * 4]);
            dstride[r] = (int)(sizeof(s_feats[0]));         // slot stride
        } else {
            src[r]     = (const char*)(tags + (size_t)bs * TT) + (k - 22) * 16;
            sstep[r]   = CH * 4;                            // 32 B per chunk
            dst0[r]    = (uint32_t)__cvta_generic_to_shared(&s_tags[0][w][s][(k - 22) * 4]);
            dstride[r] = (int)(sizeof(s_tags[0]));
        }
    }

    auto issue_chunk = [&](int c) {
        int d = c & (DEPTH - 1);
#pragma unroll
        for (int r = 0; r < 3; r++) {
            if (act[r]) {
                uint32_t dd = dst0[r] + d * dstride[r];
                const char* ss = src[r] + (size_t)c * sstep[r];
                asm volatile("cp.async.ca.shared.global [%0], [%1], 16;" :: "r"(dd), "l"(ss));
            }
        }
        asm volatile("cp.async.commit_group;" ::: "memory");
    };

    // prologue: fill the pipe
#pragma unroll
    for (int c = 0; c < DEPTH; c++) issue_chunk(c);

    float a = 0.0f, L = 0.0f, gold = 0.0f;
    int   tagprev = START_TAG;

    for (int c = 0; c < NCHK; c++) {
        asm volatile("cp.async.wait_group %0;" :: "n"(DEPTH - 1) : "memory");
        __syncwarp();

        const int d = c & (DEPTH - 1);
        const float* sf = s_feats[d][w][g];
        const int*   st = s_tags [d][w][g];

        if (c == 0) {
            // t = 0: only prev = START survives (everything else is exp(-10000) == 0 in fp32)
            float f0 = sf[j];
            a = __expf(s_trans[j * KTAGS + START_TAG] + f0);
            int tg0 = st[0];
            if (j == tg0) gold += f0 + s_trans[tg0 * KTAGS + START_TAG];
            tagprev = tg0;
#pragma unroll
            for (int tc = 1; tc < CH; tc++)
                crf_step<false>(sf[tc * KTAGS + j], st[tc], s_trans, E, base, j, a, gold, tagprev, L);
        } else {
            crf_step<true>(sf[j], st[0], s_trans, E, base, j, a, gold, tagprev, L);
#pragma unroll
            for (int tc = 1; tc < CH; tc++)
                crf_step<false>(sf[tc * KTAGS + j], st[tc], s_trans, E, base, j, a, gold, tagprev, L);
        }

        __syncwarp();
        if (c + DEPTH < NCHK) issue_chunk(c + DEPTH);
        else asm volatile("cp.async.commit_group;" ::: "memory");  // keep group count uniform
    }

    // finalize: forward = L + log( sum_j a_j * exp(trans[STOP, j]) )
    float term = a * __expf(s_trans[STOP_TAG * KTAGS + j]);
    float fsum = 0.0f, gsum = 0.0f;
#pragma unroll
    for (int p = 0; p < NST; p++) {
        fsum += __shfl_sync(0xffffffffu, term, base + p);
        gsum += __shfl_sync(0xffffffffu, gold, base + p);
    }
    float gold_total = gsum + s_trans[STOP_TAG * KTAGS + tagprev];  // + trans[STOP, tag_{T-1}]
    float res = L + __logf(fsum) - gold_total;

    if (lane == base && b < BB) out[b] = res;
}

extern "C" void kernel_launch(void* const* d_in, const int* in_sizes, int n_in,
                              void* d_out, int out_size)
{
    const float* feats = (const float*)d_in[0];
    const int*   tags  = (const int*)d_in[1];
    const float* trans = (const float*)d_in[2];
    float* out = (float*)d_out;

    dim3 grid((BB + SEQ_PB - 1) / SEQ_PB);   // 137 blocks, single wave on 148 SMs
    dim3 block(THREADS);                     // 320 threads = 10 warps = 30 sequences
    crf_nll_kernel<<<grid, block>>>(feats, tags, trans, out);
}

// round 3
// speedup vs baseline: 1.1845x; 1.1845x over previous
#include <cuda_runtime.h>
#include <cuda_bf16.h>
#include <cstdint>

#define KTAGS 11
#define NST   9
#define TT    2048
#define BB    4096
#define CH    8              // steps per chunk
#define NCHK  (TT / CH)      // 256
#define DEPTH 4
#define WARPS_PB 3
#define SEQ_PW   10          // sequences per warp (3 lanes each, 30 active lanes)
#define SEQ_PB   (WARPS_PB * SEQ_PW)   // 30
#define THREADS  (WARPS_PB * 32)       // 96
#define FSTRIDE  92          // padded floats per seq-chunk slot (bank spread + 16B align)
#define START_TAG 10
#define STOP_TAG  9

__global__ void __launch_bounds__(THREADS, 1)
crf_nll_kernel(const float* __restrict__ feats,
               const int*   __restrict__ tags,
               const float* __restrict__ trans,
               float* __restrict__ out)
{
    __shared__ __align__(16) float s_feats[DEPTH][WARPS_PB][SEQ_PW][FSTRIDE]; // 44160 B
    __shared__ __align__(16) int   s_tags [DEPTH][WARPS_PB][SEQ_PW][CH];      //  3840 B
    __shared__ float s_trans[KTAGS * KTAGS];                                  //   484 B

    const int tid = threadIdx.x;
    if (tid < KTAGS * KTAGS) s_trans[tid] = trans[tid];
    __syncthreads();

    const int w    = tid >> 5;
    const int lane = tid & 31;
    // lane -> (group, k). Lanes 30,31 shadow group 0 lanes 0,1 (results discarded).
    int grp, k;
    if (lane < 30) { grp = lane / 3; k = lane - 3 * grp; }
    else           { grp = 0;        k = lane - 30;      }
    const int glane = 3 * grp;                 // group base lane
    const int k1 = (k + 1) % 3, k2 = (k + 2) % 3;
    const int peer1 = glane + k1, peer2 = glane + k2;
    const int row0 = 3 * k;                    // this lane's first tag row
    const int b = blockIdx.x * SEQ_PB + w * SEQ_PW + grp;
    const bool writer = (lane < 30) && (k == 0) && (b < BB);

    // E[i][q] = exp(trans[row0+i][col(q)]), columns permuted to match gather order:
    // q 0..2 -> own tags 3k.., 3..5 -> peer1 tags 3k1.., 6..8 -> peer2 tags 3k2..
    float E[3][9];
#pragma unroll
    for (int i = 0; i < 3; i++) {
        const float* tr = &s_trans[(row0 + i) * KTAGS];
#pragma unroll
        for (int q = 0; q < 3; q++) {
            E[i][q]     = __expf(tr[3 * k  + q]);
            E[i][3 + q] = __expf(tr[3 * k1 + q]);
            E[i][6 + q] = __expf(tr[3 * k2 + q]);
        }
    }
    // start / stop vectors for this lane's rows
    float SV[3], ES[3];
#pragma unroll
    for (int i = 0; i < 3; i++) {
        SV[i] = s_trans[(row0 + i) * KTAGS + START_TAG];
        ES[i] = __expf(s_trans[STOP_TAG * KTAGS + (row0 + i)]);
    }

    // ---- cp.async plan: 240 16B units per warp-chunk (10 seqs x (22 feat + 2 tag)) ----
    const char* srcp[8];
    uint32_t    dstp[8];
    int         sadv[8];
    int         dadv[8];
    bool        act [8];
#pragma unroll
    for (int r = 0; r < 8; r++) {
        int u = lane + 32 * r;
        act[r] = (u < 240);
        int uu = act[r] ? u : 0;
        int s  = uu / 24;
        int kk = uu % 24;
        int bs = blockIdx.x * SEQ_PB + w * SEQ_PW + s;
        if (bs >= BB) bs = BB - 1;
        if (kk < 22) {
            srcp[r] = (const char*)feats + (size_t)bs * TT * KTAGS * 4 + kk * 16;
            sadv[r] = CH * KTAGS * 4;   // 352 B per chunk
            dstp[r] = (uint32_t)__cvta_generic_to_shared(&s_feats[0][w][s][kk * 4]);
            dadv[r] = (int)sizeof(s_feats[0]);
        } else {
            srcp[r] = (const char*)tags + (size_t)bs * TT * 4 + (kk - 22) * 16;
            sadv[r] = CH * 4;           // 32 B per chunk
            dstp[r] = (uint32_t)__cvta_generic_to_shared(&s_tags[0][w][s][(kk - 22) * 4]);
            dadv[r] = (int)sizeof(s_tags[0]);
        }
    }

    auto issue_chunk = [&](int c) {
        int d = c & (DEPTH - 1);
#pragma unroll
        for (int r = 0; r < 8; r++) {
            if (act[r]) {
                uint32_t dd = dstp[r] + d * dadv[r];
                const char* ss = srcp[r] + c * sadv[r];
                asm volatile("cp.async.ca.shared.global [%0], [%1], 16;" :: "r"(dd), "l"(ss));
            }
        }
        asm volatile("cp.async.commit_group;" ::: "memory");
    };

#pragma unroll
    for (int c = 0; c < DEPTH; c++) issue_chunk(c);

    float a0 = 0.f, a1 = 0.f, a2 = 0.f;
    float L = 0.f, goldE = 0.f, goldT = 0.f;
    int   tagprev = START_TAG;

    for (int c = 0; c < NCHK; c++) {
        asm volatile("cp.async.wait_group %0;" :: "n"(DEPTH - 1) : "memory");
        __syncwarp();

        const int d = c & (DEPTH - 1);
        const float* sf = &s_feats[d][w][grp][0];
        const int*   st = &s_tags [d][w][grp][0];

        int tc0 = 0;
        if (c == 0) {
            // t = 0: only prev = START survives (other prevs carry exp(-10000) == 0)
            float f0 = sf[row0 + 0], f1 = sf[row0 + 1], f2 = sf[row0 + 2];
            a0 = __expf(SV[0] + f0);
            a1 = __expf(SV[1] + f1);
            a2 = __expf(SV[2] + f2);
            int tg = st[0];
            unsigned dd = (unsigned)(tg - row0);
            float fsel = f0; if (dd == 1u) fsel = f1; if (dd == 2u) fsel = f2;
            if (dd < 3u) goldE += fsel;
            goldT += s_trans[tg * KTAGS + START_TAG];
            tagprev = tg;
            tc0 = 1;
        }

#pragma unroll
        for (int tc = 0; tc < CH; tc++) {
            if (tc < tc0) continue;
            const bool donorm = (tc == 0);   // only on c>0 chunk boundaries
            const float* fr = &sf[tc * KTAGS + row0];
            float f0 = fr[0], f1 = fr[1], f2 = fr[2];
            int   tg = st[tc];

            // gather the full 9-state vector (register order matches E permutation)
            float b0 = __shfl_sync(0xffffffffu, a0, peer1);
            float b1 = __shfl_sync(0xffffffffu, a1, peer1);
            float b2 = __shfl_sync(0xffffffffu, a2, peer1);
            float c0 = __shfl_sync(0xffffffffu, a0, peer2);
            float c1 = __shfl_sync(0xffffffffu, a1, peer2);
            float c2 = __shfl_sync(0xffffffffu, a2, peer2);

            float s[3];
#pragma unroll
            for (int i = 0; i < 3; i++) {
                float t1 = E[i][0] * a0;
                t1 = fmaf(E[i][1], a1, t1);
                t1 = fmaf(E[i][2], a2, t1);
                float t2 = E[i][3] * b0;
                t2 = fmaf(E[i][4], b1, t2);
                t2 = fmaf(E[i][5], b2, t2);
                float t3 = E[i][6] * c0;
                t3 = fmaf(E[i][7], c1, t3);
                t3 = fmaf(E[i][8], c2, t3);
                s[i] = t1 + (t2 + t3);
            }

            float ef0 = __expf(f0), ef1 = __expf(f1), ef2 = __expf(f2);
            if (donorm) {
                float m = fmaxf(a0, a1); m = fmaxf(m, a2);
                m = fmaxf(m, b0); m = fmaxf(m, b1); m = fmaxf(m, b2);
                m = fmaxf(m, c0); m = fmaxf(m, c1); m = fmaxf(m, c2);
                L += __logf(m);
                float r = 1.0f / m;
                ef0 *= r; ef1 *= r; ef2 *= r;
            }
            a0 = ef0 * s[0];
            a1 = ef1 * s[1];
            a2 = ef2 * s[2];

            // gold score
            unsigned dd = (unsigned)(tg - row0);
            float fsel = f0; if (dd == 1u) fsel = f1; if (dd == 2u) fsel = f2;
            if (dd < 3u) goldE += fsel;
            goldT += s_trans[tg * KTAGS + tagprev];   // group-uniform value
            tagprev = tg;
        }

        __syncwarp();
        if (c + DEPTH < NCHK) issue_chunk(c + DEPTH);
        else asm volatile("cp.async.commit_group;" ::: "memory");
    }

    // finalize: forward = L + log( sum_p a_p * exp(trans[STOP, p]) )
    float term = a0 * ES[0];
    term = fmaf(a1, ES[1], term);
    term = fmaf(a2, ES[2], term);
    float fsum = term + __shfl_sync(0xffffffffu, term, peer1)
                      + __shfl_sync(0xffffffffu, term, peer2);
    float ge = goldE + __shfl_sync(0xffffffffu, goldE, peer1)
                     + __shfl_sync(0xffffffffu, goldE, peer2);
    float gold_total = ge + goldT + s_trans[STOP_TAG * KTAGS + tagprev];
    float res = L + __logf(fsum) - gold_total;

    if (writer) out[b] = res;
}

extern "C" void kernel_launch(void* const* d_in, const int* in_sizes, int n_in,
                              void* d_out, int out_size)
{
    const float* feats = (const float*)d_in[0];
    const int*   tags  = (const int*)d_in[1];
    const float* trans = (const float*)d_in[2];
    float* out = (float*)d_out;

    dim3 grid((BB + SEQ_PB - 1) / SEQ_PB);   // 137 blocks, single wave
    dim3 block(THREADS);                     // 96 threads = 3 warps = 30 sequences
    crf_nll_kernel<<<grid, block>>>(feats, tags, trans, out);
}

// round 4
// speedup vs baseline: 1.1882x; 1.0031x over previous
#include <cuda_runtime.h>
#include <cuda_bf16.h>
#include <cstdint>

#define KTAGS 11
#define NST   9
#define TT    2048
#define BB    4096
#define CH    8              // steps per chunk
#define NCHK  (TT / CH)      // 256
#define DEPTH 4
#define WARPS_PB 3
#define SEQ_PW   10          // sequences per warp (3 lanes each, 30 active lanes)
#define SEQ_PB   (WARPS_PB * SEQ_PW)   // 30
#define THREADS  (WARPS_PB * 32)       // 96
#define FSTRIDE  92          // padded floats per seq-chunk slot (bank spread + 16B align)
#define START_TAG 10
#define STOP_TAG  9

__global__ void __launch_bounds__(THREADS, 1)
crf_nll_kernel(const float* __restrict__ feats,
               const int*   __restrict__ tags,
               const float* __restrict__ trans,
               float* __restrict__ out)
{
    __shared__ __align__(16) float s_feats[DEPTH][WARPS_PB][SEQ_PW][FSTRIDE]; // 44160 B
    __shared__ __align__(16) int   s_tags [DEPTH][WARPS_PB][SEQ_PW][CH];      //  3840 B
    __shared__ float s_trans[KTAGS * KTAGS];                                  //   484 B

    const int tid = threadIdx.x;
    if (tid < KTAGS * KTAGS) s_trans[tid] = trans[tid];
    __syncthreads();

    const int w    = tid >> 5;
    const int lane = tid & 31;
    // lane -> (group, k). Lanes 30,31 shadow group 0 lanes 0,1 (results discarded).
    int grp, k;
    if (lane < 30) { grp = lane / 3; k = lane - 3 * grp; }
    else           { grp = 0;        k = lane - 30;      }
    const int glane = 3 * grp;                 // group base lane
    const int k1 = (k + 1) % 3, k2 = (k + 2) % 3;
    const int peer1 = glane + k1, peer2 = glane + k2;
    const int row0 = 3 * k;                    // this lane's first tag row
    const int b = blockIdx.x * SEQ_PB + w * SEQ_PW + grp;
    const bool writer = (lane < 30) && (k == 0) && (b < BB);

    // E[i][q] = exp(trans[row0+i][col(q)]), columns permuted to match gather order:
    // q 0..2 -> own tags 3k.., 3..5 -> peer1 tags 3k1.., 6..8 -> peer2 tags 3k2..
    float E[3][9];
#pragma unroll
    for (int i = 0; i < 3; i++) {
        const float* tr = &s_trans[(row0 + i) * KTAGS];
#pragma unroll
        for (int q = 0; q < 3; q++) {
            E[i][q]     = __expf(tr[3 * k  + q]);
            E[i][3 + q] = __expf(tr[3 * k1 + q]);
            E[i][6 + q] = __expf(tr[3 * k2 + q]);
        }
    }
    // start / stop vectors for this lane's rows
    float SV[3], ES[3];
#pragma unroll
    for (int i = 0; i < 3; i++) {
        SV[i] = s_trans[(row0 + i) * KTAGS + START_TAG];
        ES[i] = __expf(s_trans[STOP_TAG * KTAGS + (row0 + i)]);
    }

    // ---- cp.async plan: 240 16B units per warp-chunk (10 seqs x (22 feat + 2 tag)) ----
    const char* srcp[8];
    uint32_t    dstp[8];
    int         sadv[8];
    int         dadv[8];
    bool        act [8];
#pragma unroll
    for (int r = 0; r < 8; r++) {
        int u = lane + 32 * r;
        act[r] = (u < 240);
        int uu = act[r] ? u : 0;
        int s  = uu / 24;
        int kk = uu % 24;
        int bs = blockIdx.x * SEQ_PB + w * SEQ_PW + s;
        if (bs >= BB) bs = BB - 1;
        if (kk < 22) {
            srcp[r] = (const char*)feats + (size_t)bs * TT * KTAGS * 4 + kk * 16;
            sadv[r] = CH * KTAGS * 4;   // 352 B per chunk
            dstp[r] = (uint32_t)__cvta_generic_to_shared(&s_feats[0][w][s][kk * 4]);
            dadv[r] = (int)sizeof(s_feats[0]);
        } else {
            srcp[r] = (const char*)tags + (size_t)bs * TT * 4 + (kk - 22) * 16;
            sadv[r] = CH * 4;           // 32 B per chunk
            dstp[r] = (uint32_t)__cvta_generic_to_shared(&s_tags[0][w][s][(kk - 22) * 4]);
            dadv[r] = (int)sizeof(s_tags[0]);
        }
    }

    auto issue_chunk = [&](int c) {
        int d = c & (DEPTH - 1);
#pragma unroll
        for (int r = 0; r < 8; r++) {
            if (act[r]) {
                uint32_t dd = dstp[r] + d * dadv[r];
                const char* ss = srcp[r] + c * sadv[r];
                asm volatile("cp.async.ca.shared.global [%0], [%1], 16;" :: "r"(dd), "l"(ss));
            }
        }
        asm volatile("cp.async.commit_group;" ::: "memory");
    };

#pragma unroll
    for (int c = 0; c < DEPTH; c++) issue_chunk(c);

    float a0 = 0.f, a1 = 0.f, a2 = 0.f;
    float L = 0.f, goldE = 0.f, goldT = 0.f;
    int   tagprev = START_TAG;

    for (int c = 0; c < NCHK; c++) {
        asm volatile("cp.async.wait_group %0;" :: "n"(DEPTH - 1) : "memory");
        __syncwarp();

        const int d = c & (DEPTH - 1);
        const float* sf = &s_feats[d][w][grp][0];
        const int*   st = &s_tags [d][w][grp][0];

        int tc0 = 0;
        if (c == 0) {
            // t = 0: only prev = START survives (other prevs carry exp(-10000) == 0)
            float f0 = sf[row0 + 0], f1 = sf[row0 + 1], f2 = sf[row0 + 2];
            a0 = __expf(SV[0] + f0);
            a1 = __expf(SV[1] + f1);
            a2 = __expf(SV[2] + f2);
            int tg = st[0];
            unsigned dd = (unsigned)(tg - row0);
            float fsel = f0; if (dd == 1u) fsel = f1; if (dd == 2u) fsel = f2;
            if (dd < 3u) goldE += fsel;
            goldT += s_trans[tg * KTAGS + START_TAG];
            tagprev = tg;
            tc0 = 1;
        }

#pragma unroll
        for (int tc = 0; tc < CH; tc++) {
            if (tc < tc0) continue;
            const bool donorm = (tc == 0);   // only on c>0 chunk boundaries
            const float* fr = &sf[tc * KTAGS + row0];
            float f0 = fr[0], f1 = fr[1], f2 = fr[2];
            int   tg = st[tc];

            // gather the full 9-state vector (register order matches E permutation)
            float b0 = __shfl_sync(0xffffffffu, a0, peer1);
            float b1 = __shfl_sync(0xffffffffu, a1, peer1);
            float b2 = __shfl_sync(0xffffffffu, a2, peer1);
            float c0 = __shfl_sync(0xffffffffu, a0, peer2);
            float c1 = __shfl_sync(0xffffffffu, a1, peer2);
            float c2 = __shfl_sync(0xffffffffu, a2, peer2);

            float s[3];
#pragma unroll
            for (int i = 0; i < 3; i++) {
                float t1 = E[i][0] * a0;
                t1 = fmaf(E[i][1], a1, t1);
                t1 = fmaf(E[i][2], a2, t1);
                float t2 = E[i][3] * b0;
                t2 = fmaf(E[i][4], b1, t2);
                t2 = fmaf(E[i][5], b2, t2);
                float t3 = E[i][6] * c0;
                t3 = fmaf(E[i][7], c1, t3);
                t3 = fmaf(E[i][8], c2, t3);
                s[i] = t1 + (t2 + t3);
            }

            float ef0 = __expf(f0), ef1 = __expf(f1), ef2 = __expf(f2);
            if (donorm) {
                float m = fmaxf(a0, a1); m = fmaxf(m, a2);
                m = fmaxf(m, b0); m = fmaxf(m, b1); m = fmaxf(m, b2);
                m = fmaxf(m, c0); m = fmaxf(m, c1); m = fmaxf(m, c2);
                L += __logf(m);
                float r = 1.0f / m;
                ef0 *= r; ef1 *= r; ef2 *= r;
            }
            a0 = ef0 * s[0];
            a1 = ef1 * s[1];
            a2 = ef2 * s[2];

            // gold score
            unsigned dd = (unsigned)(tg - row0);
            float fsel = f0; if (dd == 1u) fsel = f1; if (dd == 2u) fsel = f2;
            if (dd < 3u) goldE += fsel;
            goldT += s_trans[tg * KTAGS + tagprev];   // group-uniform value
            tagprev = tg;
        }

        __syncwarp();
        if (c + DEPTH < NCHK) issue_chunk(c + DEPTH);
        else asm volatile("cp.async.commit_group;" ::: "memory");
    }

    // finalize: forward = L + log( sum_p a_p * exp(trans[STOP, p]) )
    float term = a0 * ES[0];
    term = fmaf(a1, ES[1], term);
    term = fmaf(a2, ES[2], term);
    float fsum = term + __shfl_sync(0xffffffffu, term, peer1)
                      + __shfl_sync(0xffffffffu, term, peer2);
    float ge = goldE + __shfl_sync(0xffffffffu, goldE, peer1)
                     + __shfl_sync(0xffffffffu, goldE, peer2);
    float gold_total = ge + goldT + s_trans[STOP_TAG * KTAGS + tagprev];
    float res = L + __logf(fsum) - gold_total;

    if (writer) out[b] = res;
}

extern "C" void kernel_launch(void* const* d_in, const int* in_sizes, int n_in,
                              void* d_out, int out_size)
{
    const float* feats = (const float*)d_in[0];
    const int*   tags  = (const int*)d_in[1];
    const float* trans = (const float*)d_in[2];
    float* out = (float*)d_out;

    dim3 grid((BB + SEQ_PB - 1) / SEQ_PB);   // 137 blocks, single wave
    dim3 block(THREADS);                     // 96 threads = 3 warps = 30 sequences
    crf_nll_kernel<<<grid, block>>>(feats, tags, trans, out);
}